// round 16
// baseline (speedup 1.0000x reference)
#include <cuda_runtime.h>
#include <cuda_bf16.h>
#include <math.h>

#define BB 4
#define NN 8192
#define SS 2048
#define CF 64
#define OUTCH 384

#define P1 131072
#define P2 262144
#define P3 524288
#define PTOT 917504   // P1+P2+P3
#define NQ (BB * SS)  // 8192 queries per scale

#define FPS_CL 8          // CTAs per batch (cluster size)
#define FPS_PTS 1024      // points per CTA
#define FPS_THR 256

// ---------------- scratch (__device__ globals; no allocation) ----------------
__device__ float g_featsT[(long)BB * NN * CF];     // [b][n][c]
__device__ float g_xyzT[(long)BB * 3 * NN];        // [b][d][n]
__device__ float g_pn2[(long)BB * NN];             // |p|^2
__device__ float g_newxyz[(long)BB * SS * 3];      // centers
__device__ float g_q2[(long)BB * SS];              // |q|^2
__device__ int   g_ballidx[(long)BB * SS * 112];   // 16+32+64 per query
__device__ float g_bufA[(long)96 * PTOT];          // 96 x 917504
__device__ float g_bufB[(long)64 * PTOT];          // 64 x 917504
__device__ float g_mmax[(long)128 * 3 * NQ];       // [o][scale*NQ+q]
__device__ float g_mmin[(long)128 * 3 * NQ];
__device__ double g_stats9[9][256];                // [scale*3+layer][sum | sumsq]
__device__ float g_a9[9 * 128];
__device__ float g_beta9[9 * 128];

// ---------------- fused prep: transpose features + xyz SoA + |p|^2 ----------------
__global__ void fused_prep_kernel(const float* __restrict__ f,
                                  const float* __restrict__ xyz) {
    __shared__ float tile[32][33];
    int b = blockIdx.z;
    int n0 = blockIdx.x * 32, c0 = blockIdx.y * 32;
    int x = threadIdx.x, y = threadIdx.y;
    for (int r = y; r < 32; r += 8)
        tile[r][x] = f[((long)b * CF + c0 + r) * NN + n0 + x];
    if (blockIdx.y == 0) {
        int i = (blockIdx.z * (NN / 32) + blockIdx.x) * 256 + (threadIdx.y * 32 + threadIdx.x);
        if (i < BB * NN) {
            int bb = i / NN, n = i % NN;
            float px = xyz[(long)i * 3 + 0];
            float py = xyz[(long)i * 3 + 1];
            float pz = xyz[(long)i * 3 + 2];
            g_xyzT[((long)bb * 3 + 0) * NN + n] = px;
            g_xyzT[((long)bb * 3 + 1) * NN + n] = py;
            g_xyzT[((long)bb * 3 + 2) * NN + n] = pz;
            g_pn2[i] = __fadd_rn(__fadd_rn(__fmul_rn(px, px), __fmul_rn(py, py)), __fmul_rn(pz, pz));
        }
    }
    __syncthreads();
    for (int r = y; r < 32; r += 8)
        g_featsT[((long)b * NN + n0 + r) * CF + c0 + x] = tile[x][r];
}

// ---------------- FPS: cluster of 8 CTAs per batch, DSMEM candidate exchange ----------------
// Each CTA scans 1024 points from its own smem; per-iteration global argmax is
// agreed by exchanging per-CTA candidates (val,idx,x,y,z) via st.shared::cluster
// + mbarrier (release/acquire, 8 arrivals per phase). Selection predicate
// (val desc, idx asc) and all per-point arithmetic are bit-identical to the
// proven single-CTA version, so the chosen point sequence is identical.
__device__ __forceinline__ unsigned fps_smem_u32(const void* p) {
    unsigned a;
    asm("{ .reg .u64 t; cvta.to.shared.u64 t, %1; cvt.u32.u64 %0, t; }" : "=r"(a) : "l"(p));
    return a;
}

__global__ void __cluster_dims__(FPS_CL, 1, 1) __launch_bounds__(FPS_THR)
fps_cluster_kernel(const float* __restrict__ xyz, float* __restrict__ out_newxyz) {
    __shared__ float sx[FPS_PTS], sy[FPS_PTS], sz[FPS_PTS];
    __shared__ float swv[8];
    __shared__ int   swi[8];
    __shared__ __align__(16) float cand[2][FPS_CL][8];  // [buf][rank][val,idx,x,y,z,pad]
    __shared__ __align__(8) unsigned long long mbar;

    int tid = threadIdx.x;
    int lane = tid & 31, wid = tid >> 5;
    int b = blockIdx.x / FPS_CL;
    unsigned rank;
    asm("mov.u32 %0, %%cluster_ctarank;" : "=r"(rank));

    unsigned mbarA = fps_smem_u32(&mbar);

    if (tid == 0) {
        asm volatile("mbarrier.init.shared.b64 [%0], %1;" :: "r"(mbarA), "r"(FPS_CL) : "memory");
    }
    // load this CTA's slice of points
    long gbase = (long)b * NN + (long)rank * FPS_PTS;
    for (int i = tid; i < FPS_PTS; i += FPS_THR) {
        sx[i] = xyz[(gbase + i) * 3 + 0];
        sy[i] = xyz[(gbase + i) * 3 + 1];
        sz[i] = xyz[(gbase + i) * 3 + 2];
    }
    __syncthreads();
    // all CTAs' mbarriers must be initialized before any remote arrive
    asm volatile("barrier.cluster.arrive.aligned;" ::: "memory");
    asm volatile("barrier.cluster.wait.aligned;" ::: "memory");

    // initial far point = point 0 of the batch (same value for all CTAs)
    float fx = xyz[(long)b * NN * 3 + 0];
    float fy = xyz[(long)b * NN * 3 + 1];
    float fz = xyz[(long)b * NN * 3 + 2];

    float dc[4];
#pragma unroll
    for (int j = 0; j < 4; ++j) dc[j] = 3.4e38f;

    for (int it = 0; it < SS; ++it) {
        if (rank == 0 && tid == 0) {
            long q = (long)b * SS + it;
            out_newxyz[q * 3 + 0] = fx;
            out_newxyz[q * 3 + 1] = fy;
            out_newxyz[q * 3 + 2] = fz;
            g_newxyz[q * 3 + 0] = fx;
            g_newxyz[q * 3 + 1] = fy;
            g_newxyz[q * 3 + 2] = fz;
            g_q2[q] = __fadd_rn(__fadd_rn(__fmul_rn(fx, fx), __fmul_rn(fy, fy)), __fmul_rn(fz, fz));
        }
        float mv = -1.0f;
        int mi = 0;
#pragma unroll
        for (int j = 0; j < 4; ++j) {
            int il = tid + j * FPS_THR;
            float dx = __fadd_rn(sx[il], -fx);
            float dy = __fadd_rn(sy[il], -fy);
            float dz = __fadd_rn(sz[il], -fz);
            float d = __fadd_rn(__fadd_rn(__fmul_rn(dx, dx), __fmul_rn(dy, dy)), __fmul_rn(dz, dz));
            float dn = fminf(dc[j], d);
            dc[j] = dn;
            if (dn > mv) { mv = dn; mi = (int)rank * FPS_PTS + il; }
        }
#pragma unroll
        for (int off = 16; off > 0; off >>= 1) {
            float ov = __shfl_down_sync(0xffffffffu, mv, off);
            int   oi = __shfl_down_sync(0xffffffffu, mi, off);
            if (ov > mv || (ov == mv && oi < mi)) { mv = ov; mi = oi; }
        }
        if (lane == 0) { swv[wid] = mv; swi[wid] = mi; }
        __syncthreads();
        int buf = it & 1;
        if (tid == 0) {
            float bv = swv[0];
            int   bi = swi[0];
#pragma unroll
            for (int w = 1; w < 8; ++w) {
                float ov = swv[w];
                int   oi = swi[w];
                if (ov > bv || (ov == bv && oi < bi)) { bv = ov; bi = oi; }
            }
            int il = bi - (int)rank * FPS_PTS;
            unsigned uv = __float_as_uint(bv);
            unsigned ui = (unsigned)bi;
            unsigned ux = __float_as_uint(sx[il]);
            unsigned uy = __float_as_uint(sy[il]);
            unsigned uz = __float_as_uint(sz[il]);
            unsigned slotA = fps_smem_u32(&cand[buf][rank][0]);
#pragma unroll
            for (int c = 0; c < FPS_CL; ++c) {
                unsigned rslot, rbar;
                asm volatile("mapa.shared::cluster.u32 %0, %1, %2;" : "=r"(rslot) : "r"(slotA), "r"(c));
                asm volatile("st.shared::cluster.v4.b32 [%0], {%1, %2, %3, %4};"
                             :: "r"(rslot), "r"(uv), "r"(ui), "r"(ux), "r"(uy) : "memory");
                asm volatile("st.shared::cluster.b32 [%0], %1;"
                             :: "r"(rslot + 16), "r"(uz) : "memory");
                asm volatile("mapa.shared::cluster.u32 %0, %1, %2;" : "=r"(rbar) : "r"(mbarA), "r"(c));
                asm volatile("mbarrier.arrive.release.cluster.shared::cluster.b64 _, [%0];"
                             :: "r"(rbar) : "memory");
            }
        }
        // wait for all 8 CTA candidates (acquire, cluster scope)
        {
            unsigned parity = (unsigned)(it & 1);
            unsigned done;
            asm volatile(
                "{\n\t.reg .pred p;\n\t"
                "mbarrier.try_wait.parity.acquire.cluster.shared::cta.b64 p, [%1], %2, 0x989680;\n\t"
                "selp.b32 %0, 1, 0, p;\n\t}"
                : "=r"(done) : "r"(mbarA), "r"(parity) : "memory");
            while (!done) {
                asm volatile(
                    "{\n\t.reg .pred p;\n\t"
                    "mbarrier.try_wait.parity.acquire.cluster.shared::cta.b64 p, [%1], %2, 0x989680;\n\t"
                    "selp.b32 %0, 1, 0, p;\n\t}"
                    : "=r"(done) : "r"(mbarA), "r"(parity) : "memory");
            }
        }
        // every thread reduces the 8 candidates (identical result everywhere)
        float bv = cand[buf][0][0];
        int   bi = __float_as_int(cand[buf][0][1]);
        float bx = cand[buf][0][2], by = cand[buf][0][3], bz = cand[buf][0][4];
#pragma unroll
        for (int c = 1; c < FPS_CL; ++c) {
            float ov = cand[buf][c][0];
            int   oi = __float_as_int(cand[buf][c][1]);
            if (ov > bv || (ov == bv && oi < bi)) {
                bv = ov; bi = oi;
                bx = cand[buf][c][2]; by = cand[buf][c][3]; bz = cand[buf][c][4];
            }
        }
        fx = bx; fy = by; fz = bz;
    }
    asm volatile("barrier.cluster.arrive.aligned;" ::: "memory");
    asm volatile("barrier.cluster.wait.aligned;" ::: "memory");
}

// ---------------- ball query: 1 warp per (b, s), all 3 radii ----------------
__global__ void ballq_kernel() {
    int warp = (blockIdx.x * blockDim.x + threadIdx.x) >> 5;
    int lane = threadIdx.x & 31;
    if (warp >= BB * SS) return;
    int b = warp / SS;
    float qx = g_newxyz[(long)warp * 3 + 0];
    float qy = g_newxyz[(long)warp * 3 + 1];
    float qz = g_newxyz[(long)warp * 3 + 2];
    float q2 = g_q2[warp];
    const float rr0 = 0.1f * 0.1f, rr1 = 0.2f * 0.2f, rr2 = 0.4f * 0.4f;
    int c0 = 0, c1 = 0, c2 = 0;
    int f0 = NN - 1, f1 = NN - 1, f2 = NN - 1;
    int* ball = g_ballidx + (long)warp * 112;
    unsigned lanemask = (1u << lane) - 1u;

    const float* px0 = &g_xyzT[((long)b * 3 + 0) * NN];
    const float* py0 = &g_xyzT[((long)b * 3 + 1) * NN];
    const float* pz0 = &g_xyzT[((long)b * 3 + 2) * NN];
    const float* pn2a = &g_pn2[(long)b * NN];

    for (int n0 = 0; n0 < NN; n0 += 32) {
        int n = n0 + lane;
        float px = px0[n], py = py0[n], pz = pz0[n];
        float pn2 = pn2a[n];
        float dot = __fadd_rn(__fadd_rn(__fmul_rn(qx, px), __fmul_rn(qy, py)), __fmul_rn(qz, pz));
        float d2 = __fadd_rn(__fadd_rn(q2, pn2), -__fmul_rn(2.0f, dot));
        bool in0 = d2 < rr0, in1 = d2 < rr1, in2 = d2 < rr2;
        unsigned m0 = __ballot_sync(0xffffffffu, in0);
        unsigned m1 = __ballot_sync(0xffffffffu, in1);
        unsigned m2 = __ballot_sync(0xffffffffu, in2);
        if (c0 < 16) {
            if (c0 == 0 && m0) f0 = n0 + __ffs(m0) - 1;
            int pos = c0 + __popc(m0 & lanemask);
            if (in0 && pos < 16) ball[pos] = n;
            c0 = min(16, c0 + __popc(m0));
        }
        if (c1 < 32) {
            if (c1 == 0 && m1) f1 = n0 + __ffs(m1) - 1;
            int pos = c1 + __popc(m1 & lanemask);
            if (in1 && pos < 32) ball[16 + pos] = n;
            c1 = min(32, c1 + __popc(m1));
        }
        if (c2 < 64) {
            if (c2 == 0 && m2) f2 = n0 + __ffs(m2) - 1;
            int pos = c2 + __popc(m2 & lanemask);
            if (in2 && pos < 64) ball[48 + pos] = n;
            c2 = min(64, c2 + __popc(m2));
        }
        if (c0 >= 16 && c1 >= 32 && c2 >= 64) break;
    }
    for (int p = c0 + lane; p < 16; p += 32) ball[p] = f0;
    for (int p = c1 + lane; p < 32; p += 32) ball[16 + p] = f1;
    for (int p = c2 + lane; p < 64; p += 32) ball[48 + p] = f2;
}

// ---------------- grouped single-pass GEMM over all 3 scales ----------------
// W panel LDG issued FIRST (dense, front-batched) to overlap the scattered gather LDGs.
// Thread owns split columns {pg*4..+3} and {PT/2+pg*4..+3}: LDS is dense 16B/lane.
template <int O, int C, int PT, int TO, int LAYER, bool FOLD, bool GATHER, bool MAXOUT>
__global__ void __launch_bounds__(256) gemm_t(
    const float* __restrict__ Wg, const float* __restrict__ X,
    float* __restrict__ Y) {
    constexpr int TP = 8;
    constexpr int PG = PT / TP;
    constexpr int OG = O / TO;
    constexpr int OP = O + 4;     // padded W stride
    static_assert(PG * OG == 256, "bad tiling");
    constexpr int NB0 = P1 / PT, NB1 = P2 / PT;

    extern __shared__ float smx[];
    float* Xs = smx;              // [C][PT]
    float* Ws = smx + C * PT;     // [C][O+4]

    int bs = blockIdx.x;
    int scale = (bs < NB0) ? 0 : ((bs < NB0 + NB1) ? 1 : 2);
    int blk = bs - ((scale == 0) ? 0 : ((scale == 1) ? NB0 : NB0 + NB1));
    long colOff = (scale == 0) ? 0L : ((scale == 1) ? (long)P1 : (long)(P1 + P2));
    long p0 = colOff + (long)blk * PT;
    const float* W = Wg + (long)scale * O * C;
    double* statsOut = &g_stats9[scale * 3 + LAYER][0];
    const float* aArr = &g_a9[(scale * 3 + LAYER - 1) * 128];
    const float* bArr = &g_beta9[(scale * 3 + LAYER - 1) * 128];

    int tid = threadIdx.x;

    // W: linear coalesced LDG first (front-batched MLP), transposed STS
#pragma unroll 4
    for (int i = tid; i < C * O; i += 256) {
        int o = i / C;
        int c = i - o * C;
        Ws[c * OP + o] = W[i];
    }

    if (GATHER) {
        static_assert(!GATHER || PT == 256, "gather wants PT==256");
        int off = (scale == 0) ? 0 : ((scale == 1) ? 16 : 48);
        long pl = (p0 + tid) - colOff;
        int q = (int)(pl >> (4 + scale));
        int k = (int)(pl & ((16 << scale) - 1));
        int b = q >> 11;  // q / SS
        int idx = g_ballidx[(long)q * 112 + off + k];
#pragma unroll
        for (int c = 0; c < 3; ++c)
            Xs[c * PT + tid] = g_xyzT[((long)b * 3 + c) * NN + idx] - g_newxyz[(long)q * 3 + c];
        const float4* fr = (const float4*)&g_featsT[((long)b * NN + idx) * CF];
#pragma unroll
        for (int c4 = 0; c4 < CF / 4; ++c4) {
            float4 v = fr[c4];
            Xs[(3 + c4 * 4 + 0) * PT + tid] = v.x;
            Xs[(3 + c4 * 4 + 1) * PT + tid] = v.y;
            Xs[(3 + c4 * 4 + 2) * PT + tid] = v.z;
            Xs[(3 + c4 * 4 + 3) * PT + tid] = v.w;
        }
    } else {
#pragma unroll 4
        for (int i = tid; i < C * (PT / 4); i += 256) {
            int c = i / (PT / 4);
            int col = i - c * (PT / 4);
            float4 v = *(const float4*)&X[(long)c * PTOT + p0 + col * 4];
            if (FOLD) {
                float a = aArr[c], be = bArr[c];
                v.x = fmaxf(0.0f, fmaf(a, v.x, be));
                v.y = fmaxf(0.0f, fmaf(a, v.y, be));
                v.z = fmaxf(0.0f, fmaf(a, v.z, be));
                v.w = fmaxf(0.0f, fmaf(a, v.w, be));
            }
            *(float4*)&Xs[c * PT + col * 4] = v;
        }
    }
    __syncthreads();

    int pg = tid % PG;
    int og = tid / PG;

    unsigned long long accq[TO][TP / 2];
#pragma unroll
    for (int i = 0; i < TO; ++i)
#pragma unroll
        for (int j = 0; j < TP / 2; ++j) accq[i][j] = 0ull;

    // dense split addressing: 16B/lane, conflict-free
    const float* xpA = Xs + pg * 4;
    const float* xpB = Xs + PT / 2 + pg * 4;
    const float* wp = Ws + og * TO;
#pragma unroll 4
    for (int cc = 0; cc < C; ++cc) {
        ulonglong2 xa = *(const ulonglong2*)&xpA[cc * PT];
        ulonglong2 xb = *(const ulonglong2*)&xpB[cc * PT];
        unsigned long long xq0 = xa.x, xq1 = xa.y, xq2 = xb.x, xq3 = xb.y;
        float wv[TO];
        if (TO == 8) {
            float4 w0 = *(const float4*)&wp[cc * OP];
            float4 w1 = *(const float4*)&wp[cc * OP + 4];
            wv[0] = w0.x; wv[1] = w0.y; wv[2] = w0.z; wv[3] = w0.w;
            wv[4] = w1.x; wv[5] = w1.y; wv[6] = w1.z; wv[7] = w1.w;
        } else {
#pragma unroll
            for (int i = 0; i < TO; ++i) wv[i] = wp[cc * OP + i];
        }
#pragma unroll
        for (int i = 0; i < TO; ++i) {
            unsigned long long wq;
            unsigned int wu = __float_as_uint(wv[i]);
            asm("mov.b64 %0, {%1, %1};" : "=l"(wq) : "r"(wu));
            asm("fma.rn.f32x2 %0, %1, %2, %0;" : "+l"(accq[i][0]) : "l"(wq), "l"(xq0));
            asm("fma.rn.f32x2 %0, %1, %2, %0;" : "+l"(accq[i][1]) : "l"(wq), "l"(xq1));
            asm("fma.rn.f32x2 %0, %1, %2, %0;" : "+l"(accq[i][2]) : "l"(wq), "l"(xq2));
            asm("fma.rn.f32x2 %0, %1, %2, %0;" : "+l"(accq[i][3]) : "l"(wq), "l"(xq3));
        }
    }

    // acc[i][0..3] -> cols p0+pg*4+0..3 ; acc[i][4..7] -> cols p0+PT/2+pg*4+0..3
    float acc[TO][TP];
#pragma unroll
    for (int i = 0; i < TO; ++i)
#pragma unroll
        for (int j2 = 0; j2 < TP / 2; ++j2) {
            unsigned int lo, hi;
            asm("mov.b64 {%0, %1}, %2;" : "=r"(lo), "=r"(hi) : "l"(accq[i][j2]));
            acc[i][2 * j2]     = __uint_as_float(lo);
            acc[i][2 * j2 + 1] = __uint_as_float(hi);
        }

    int Wd = 4 << scale;                 // lanes sharing one query (K/4)
    long qA = (p0 - colOff + pg * 4) >> (4 + scale);
    long qB = (p0 - colOff + PT / 2 + pg * 4) >> (4 + scale);

#pragma unroll
    for (int i = 0; i < TO; ++i) {
        int o = og * TO + i;
        float s = 0.0f, sq = 0.0f;
#pragma unroll
        for (int j = 0; j < TP; ++j) {
            float v = acc[i][j];
            s += v;
            sq = fmaf(v, v, sq);
        }
        if (!MAXOUT) {
            float4 v0 = make_float4(acc[i][0], acc[i][1], acc[i][2], acc[i][3]);
            float4 v1 = make_float4(acc[i][4], acc[i][5], acc[i][6], acc[i][7]);
            *(float4*)&Y[(long)o * PTOT + p0 + pg * 4] = v0;
            *(float4*)&Y[(long)o * PTOT + p0 + PT / 2 + pg * 4] = v1;
        }
#pragma unroll
        for (int off = PG / 2; off > 0; off >>= 1) {
            s  += __shfl_down_sync(0xffffffffu, s, off, PG);
            sq += __shfl_down_sync(0xffffffffu, sq, off, PG);
        }
        if (pg == 0) {
            atomicAdd(&statsOut[o], (double)s);
            atomicAdd(&statsOut[128 + o], (double)sq);
        }
        if (MAXOUT) {
            float mxA = fmaxf(fmaxf(acc[i][0], acc[i][1]), fmaxf(acc[i][2], acc[i][3]));
            float mnA = fminf(fminf(acc[i][0], acc[i][1]), fminf(acc[i][2], acc[i][3]));
            float mxB = fmaxf(fmaxf(acc[i][4], acc[i][5]), fmaxf(acc[i][6], acc[i][7]));
            float mnB = fminf(fminf(acc[i][4], acc[i][5]), fminf(acc[i][6], acc[i][7]));
            for (int off = Wd >> 1; off > 0; off >>= 1) {
                mxA = fmaxf(mxA, __shfl_down_sync(0xffffffffu, mxA, off, Wd));
                mnA = fminf(mnA, __shfl_down_sync(0xffffffffu, mnA, off, Wd));
                mxB = fmaxf(mxB, __shfl_down_sync(0xffffffffu, mxB, off, Wd));
                mnB = fminf(mnB, __shfl_down_sync(0xffffffffu, mnB, off, Wd));
            }
            if ((pg & (Wd - 1)) == 0) {
                g_mmax[(long)o * (3 * NQ) + scale * NQ + qA] = mxA;
                g_mmin[(long)o * (3 * NQ) + scale * NQ + qA] = mnA;
                g_mmax[(long)o * (3 * NQ) + scale * NQ + qB] = mxB;
                g_mmin[(long)o * (3 * NQ) + scale * NQ + qB] = mnB;
            }
        }
    }
}

// ---------------- finalize BN params: one block per scale ----------------
__global__ void finalize_kernel(int L, int O, const float* __restrict__ g,
                                const float* __restrict__ b) {
    int s = blockIdx.x;
    int o = threadIdx.x;
    if (o >= O) return;
    long Pc = (s == 0) ? P1 : ((s == 1) ? P2 : P3);
    const double* st = g_stats9[s * 3 + L];
    double m = st[o] / (double)Pc;
    double var = st[128 + o] / (double)Pc - m * m;
    float aa = g[s * O + o] / sqrtf((float)var + 1e-5f);
    g_a9[(s * 3 + L) * 128 + o] = aa;
    g_beta9[(s * 3 + L) * 128 + o] = fmaf(-(float)m, aa, b[s * O + o]);
}

// ---------------- final BN+ReLU on pooled max/min ----------------
__global__ void bn_out_kernel(float* __restrict__ out) {
    int i = blockIdx.x * 256 + threadIdx.x;   // over 3*128*NQ
    int scale = i / (128 * NQ);
    int r = i - scale * (128 * NQ);
    int o = r / NQ;
    int q = r - o * NQ;
    int b = q >> 11, s = q & (SS - 1);
    float a = g_a9[(scale * 3 + 2) * 128 + o];
    float be = g_beta9[(scale * 3 + 2) * 128 + o];
    float mx = g_mmax[(long)o * (3 * NQ) + scale * NQ + q];
    float mn = g_mmin[(long)o * (3 * NQ) + scale * NQ + q];
    float v = (a >= 0.0f) ? mx : mn;
    out[((long)b * OUTCH + scale * 128 + o) * SS + s] = fmaxf(0.0f, fmaf(a, v, be));
}

// ---------------- launch ----------------
extern "C" void kernel_launch(void* const* d_in, const int* in_sizes, int n_in,
                              void* d_out, int out_size) {
    (void)in_sizes; (void)n_in; (void)out_size;
    const float* xyz   = (const float*)d_in[0];
    const float* feats = (const float*)d_in[1];
    const float* w1 = (const float*)d_in[2];
    const float* g1 = (const float*)d_in[3];
    const float* b1 = (const float*)d_in[4];
    const float* w2 = (const float*)d_in[5];
    const float* g2 = (const float*)d_in[6];
    const float* b2 = (const float*)d_in[7];
    const float* w3 = (const float*)d_in[8];
    const float* g3 = (const float*)d_in[9];
    const float* b3 = (const float*)d_in[10];
    float* out = (float*)d_out;
    float* outF = out + (long)BB * SS * 3;

    float *bufA = nullptr, *bufB = nullptr;
    double* stats = nullptr;
    cudaGetSymbolAddress((void**)&bufA, g_bufA);
    cudaGetSymbolAddress((void**)&bufB, g_bufB);
    cudaGetSymbolAddress((void**)&stats, g_stats9);

    auto g1k = gemm_t<64, 67, 256, 8, 0, false, true, false>;
    auto g2k = gemm_t<96, 64, 128, 6, 1, true, false, false>;
    auto g3k = gemm_t<128, 96, 128, 8, 2, true, false, true>;
    const int smem1 = 67 * 256 * 4 + 67 * 68 * 4;
    const int smem2 = 64 * 128 * 4 + 64 * 100 * 4;
    const int smem3 = 96 * 128 * 4 + 96 * 132 * 4;
    cudaFuncSetAttribute(g1k, cudaFuncAttributeMaxDynamicSharedMemorySize, smem1);
    cudaFuncSetAttribute(g2k, cudaFuncAttributeMaxDynamicSharedMemorySize, smem2);
    cudaFuncSetAttribute(g3k, cudaFuncAttributeMaxDynamicSharedMemorySize, smem3);

    cudaMemsetAsync(stats, 0, 9 * 256 * sizeof(double));

    // kernel launches: 1 fused_prep, 2 fps, 3 ballq, 4 g1k (profiled slot)
    dim3 tb(32, 8), tg(NN / 32, CF / 32, BB);
    fused_prep_kernel<<<tg, tb>>>(feats, xyz);
    fps_cluster_kernel<<<BB * FPS_CL, FPS_THR>>>(xyz, out);
    ballq_kernel<<<(BB * SS * 32) / 256, 256>>>();

    g1k<<<PTOT / 256, 256, smem1>>>(w1, nullptr, bufB);
    finalize_kernel<<<3, 128>>>(0, 64, g1, b1);

    g2k<<<PTOT / 128, 256, smem2>>>(w2, bufB, bufA);
    finalize_kernel<<<3, 128>>>(1, 96, g2, b2);

    g3k<<<PTOT / 128, 256, smem3>>>(w3, bufA, nullptr);
    finalize_kernel<<<3, 128>>>(2, 128, g3, b3);

    bn_out_kernel<<<3 * 128 * NQ / 256, 256>>>(outF);
}

// round 17
// speedup vs baseline: 1.6592x; 1.6592x over previous
#include <cuda_runtime.h>
#include <cuda_bf16.h>
#include <math.h>

#define BB 4
#define NN 8192
#define SS 2048
#define CF 64
#define OUTCH 384

#define P1 131072
#define P2 262144
#define P3 524288
#define PTOT 917504   // P1+P2+P3
#define NQ (BB * SS)  // 8192 queries per scale

// ---------------- scratch (__device__ globals; no allocation) ----------------
__device__ float g_featsT[(long)BB * NN * CF];     // [b][n][c]
__device__ float g_xyzT[(long)BB * 3 * NN];        // [b][d][n]
__device__ float g_pn2[(long)BB * NN];             // |p|^2
__device__ float g_newxyz[(long)BB * SS * 3];      // centers
__device__ float g_q2[(long)BB * SS];              // |q|^2
__device__ int   g_ballidx[(long)BB * SS * 112];   // 16+32+64 per query
__device__ float g_bufA[(long)96 * PTOT];          // 96 x 917504
__device__ float g_bufB[(long)64 * PTOT];          // 64 x 917504
__device__ float g_mmax[(long)128 * 3 * NQ];       // [o][scale*NQ+q]
__device__ float g_mmin[(long)128 * 3 * NQ];
__device__ double g_stats9[9][256];                // [scale*3+layer][sum | sumsq]
__device__ float g_a9[9 * 128];
__device__ float g_beta9[9 * 128];

// ---------------- fused prep: transpose features + xyz SoA + |p|^2 ----------------
__global__ void fused_prep_kernel(const float* __restrict__ f,
                                  const float* __restrict__ xyz) {
    __shared__ float tile[32][33];
    int b = blockIdx.z;
    int n0 = blockIdx.x * 32, c0 = blockIdx.y * 32;
    int x = threadIdx.x, y = threadIdx.y;
    for (int r = y; r < 32; r += 8)
        tile[r][x] = f[((long)b * CF + c0 + r) * NN + n0 + x];
    if (blockIdx.y == 0) {
        int i = (blockIdx.z * (NN / 32) + blockIdx.x) * 256 + (threadIdx.y * 32 + threadIdx.x);
        if (i < BB * NN) {
            int bb = i / NN, n = i % NN;
            float px = xyz[(long)i * 3 + 0];
            float py = xyz[(long)i * 3 + 1];
            float pz = xyz[(long)i * 3 + 2];
            g_xyzT[((long)bb * 3 + 0) * NN + n] = px;
            g_xyzT[((long)bb * 3 + 1) * NN + n] = py;
            g_xyzT[((long)bb * 3 + 2) * NN + n] = pz;
            g_pn2[i] = __fadd_rn(__fadd_rn(__fmul_rn(px, px), __fmul_rn(py, py)), __fmul_rn(pz, pz));
        }
    }
    __syncthreads();
    for (int r = y; r < 32; r += 8)
        g_featsT[((long)b * NN + n0 + r) * CF + c0 + x] = tile[x][r];
}

// ---------------- FPS: one block per batch (R13-proven 2-barrier smem version; FROZEN) ----------------
__global__ void fps_kernel(const float* __restrict__ xyz, float* __restrict__ out_newxyz) {
    extern __shared__ float sm[];
    float* sx = sm;
    float* sy = sm + NN;
    float* sz = sm + 2 * NN;
    __shared__ float swv[32];
    __shared__ int   swi[32];
    __shared__ int   sfar;

    int b = blockIdx.x;
    int tid = threadIdx.x;
    int lane = tid & 31, wid = tid >> 5;

    for (int i = tid; i < NN; i += 1024) {
        sx[i] = xyz[((long)b * NN + i) * 3 + 0];
        sy[i] = xyz[((long)b * NN + i) * 3 + 1];
        sz[i] = xyz[((long)b * NN + i) * 3 + 2];
    }
    float dcur[8];
#pragma unroll
    for (int j = 0; j < 8; ++j) dcur[j] = 3.4e38f;
    int far = 0;
    __syncthreads();

    for (int it = 0; it < SS; ++it) {
        float fx = sx[far], fy = sy[far], fz = sz[far];
        if (tid == 0) {
            long q = (long)b * SS + it;
            out_newxyz[q * 3 + 0] = fx;
            out_newxyz[q * 3 + 1] = fy;
            out_newxyz[q * 3 + 2] = fz;
            g_newxyz[q * 3 + 0] = fx;
            g_newxyz[q * 3 + 1] = fy;
            g_newxyz[q * 3 + 2] = fz;
            g_q2[q] = __fadd_rn(__fadd_rn(__fmul_rn(fx, fx), __fmul_rn(fy, fy)), __fmul_rn(fz, fz));
        }
        float mv = -1.0f;
        int mi = 0;
#pragma unroll
        for (int j = 0; j < 8; ++j) {
            int i = tid + j * 1024;
            float dx = __fadd_rn(sx[i], -fx);
            float dy = __fadd_rn(sy[i], -fy);
            float dz = __fadd_rn(sz[i], -fz);
            float d = __fadd_rn(__fadd_rn(__fmul_rn(dx, dx), __fmul_rn(dy, dy)), __fmul_rn(dz, dz));
            float dn = fminf(dcur[j], d);
            dcur[j] = dn;
            if (dn > mv) { mv = dn; mi = i; }
        }
#pragma unroll
        for (int off = 16; off > 0; off >>= 1) {
            float ov = __shfl_down_sync(0xffffffffu, mv, off);
            int   oi = __shfl_down_sync(0xffffffffu, mi, off);
            if (ov > mv || (ov == mv && oi < mi)) { mv = ov; mi = oi; }
        }
        if (lane == 0) { swv[wid] = mv; swi[wid] = mi; }
        __syncthreads();
        if (wid == 0) {
            float v = swv[lane];
            int   ii = swi[lane];
#pragma unroll
            for (int off = 16; off > 0; off >>= 1) {
                float ov = __shfl_down_sync(0xffffffffu, v, off);
                int   oi = __shfl_down_sync(0xffffffffu, ii, off);
                if (ov > v || (ov == v && oi < ii)) { v = ov; ii = oi; }
            }
            if (lane == 0) sfar = ii;
        }
        __syncthreads();
        far = sfar;
    }
}

// ---------------- ball query: 1 warp per (b, s), all 3 radii ----------------
__global__ void ballq_kernel() {
    int warp = (blockIdx.x * blockDim.x + threadIdx.x) >> 5;
    int lane = threadIdx.x & 31;
    if (warp >= BB * SS) return;
    int b = warp / SS;
    float qx = g_newxyz[(long)warp * 3 + 0];
    float qy = g_newxyz[(long)warp * 3 + 1];
    float qz = g_newxyz[(long)warp * 3 + 2];
    float q2 = g_q2[warp];
    const float rr0 = 0.1f * 0.1f, rr1 = 0.2f * 0.2f, rr2 = 0.4f * 0.4f;
    int c0 = 0, c1 = 0, c2 = 0;
    int f0 = NN - 1, f1 = NN - 1, f2 = NN - 1;
    int* ball = g_ballidx + (long)warp * 112;
    unsigned lanemask = (1u << lane) - 1u;

    const float* px0 = &g_xyzT[((long)b * 3 + 0) * NN];
    const float* py0 = &g_xyzT[((long)b * 3 + 1) * NN];
    const float* pz0 = &g_xyzT[((long)b * 3 + 2) * NN];
    const float* pn2a = &g_pn2[(long)b * NN];

    for (int n0 = 0; n0 < NN; n0 += 32) {
        int n = n0 + lane;
        float px = px0[n], py = py0[n], pz = pz0[n];
        float pn2 = pn2a[n];
        float dot = __fadd_rn(__fadd_rn(__fmul_rn(qx, px), __fmul_rn(qy, py)), __fmul_rn(qz, pz));
        float d2 = __fadd_rn(__fadd_rn(q2, pn2), -__fmul_rn(2.0f, dot));
        bool in0 = d2 < rr0, in1 = d2 < rr1, in2 = d2 < rr2;
        unsigned m0 = __ballot_sync(0xffffffffu, in0);
        unsigned m1 = __ballot_sync(0xffffffffu, in1);
        unsigned m2 = __ballot_sync(0xffffffffu, in2);
        if (c0 < 16) {
            if (c0 == 0 && m0) f0 = n0 + __ffs(m0) - 1;
            int pos = c0 + __popc(m0 & lanemask);
            if (in0 && pos < 16) ball[pos] = n;
            c0 = min(16, c0 + __popc(m0));
        }
        if (c1 < 32) {
            if (c1 == 0 && m1) f1 = n0 + __ffs(m1) - 1;
            int pos = c1 + __popc(m1 & lanemask);
            if (in1 && pos < 32) ball[16 + pos] = n;
            c1 = min(32, c1 + __popc(m1));
        }
        if (c2 < 64) {
            if (c2 == 0 && m2) f2 = n0 + __ffs(m2) - 1;
            int pos = c2 + __popc(m2 & lanemask);
            if (in2 && pos < 64) ball[48 + pos] = n;
            c2 = min(64, c2 + __popc(m2));
        }
        if (c0 >= 16 && c1 >= 32 && c2 >= 64) break;
    }
    for (int p = c0 + lane; p < 16; p += 32) ball[p] = f0;
    for (int p = c1 + lane; p < 32; p += 32) ball[16 + p] = f1;
    for (int p = c2 + lane; p < 64; p += 32) ball[48 + p] = f2;
}

// ---------------- grouped single-pass GEMM over all 3 scales ----------------
// W panel LDG issued FIRST (dense, front-batched) to overlap the scattered gather LDGs.
// Thread owns split columns {pg*4..+3} and {PT/2+pg*4..+3}: LDS is dense 16B/lane.
template <int O, int C, int PT, int TO, int LAYER, bool FOLD, bool GATHER, bool MAXOUT>
__global__ void __launch_bounds__(256) gemm_t(
    const float* __restrict__ Wg, const float* __restrict__ X,
    float* __restrict__ Y) {
    constexpr int TP = 8;
    constexpr int PG = PT / TP;
    constexpr int OG = O / TO;
    constexpr int OP = O + 4;     // padded W stride
    static_assert(PG * OG == 256, "bad tiling");
    constexpr int NB0 = P1 / PT, NB1 = P2 / PT;

    extern __shared__ float smx[];
    float* Xs = smx;              // [C][PT]
    float* Ws = smx + C * PT;     // [C][O+4]

    int bs = blockIdx.x;
    int scale = (bs < NB0) ? 0 : ((bs < NB0 + NB1) ? 1 : 2);
    int blk = bs - ((scale == 0) ? 0 : ((scale == 1) ? NB0 : NB0 + NB1));
    long colOff = (scale == 0) ? 0L : ((scale == 1) ? (long)P1 : (long)(P1 + P2));
    long p0 = colOff + (long)blk * PT;
    const float* W = Wg + (long)scale * O * C;
    double* statsOut = &g_stats9[scale * 3 + LAYER][0];
    const float* aArr = &g_a9[(scale * 3 + LAYER - 1) * 128];
    const float* bArr = &g_beta9[(scale * 3 + LAYER - 1) * 128];

    int tid = threadIdx.x;

    // W: linear coalesced LDG first (front-batched MLP), transposed STS
#pragma unroll 4
    for (int i = tid; i < C * O; i += 256) {
        int o = i / C;
        int c = i - o * C;
        Ws[c * OP + o] = W[i];
    }

    if (GATHER) {
        static_assert(!GATHER || PT == 256, "gather wants PT==256");
        int off = (scale == 0) ? 0 : ((scale == 1) ? 16 : 48);
        long pl = (p0 + tid) - colOff;
        int q = (int)(pl >> (4 + scale));
        int k = (int)(pl & ((16 << scale) - 1));
        int b = q >> 11;  // q / SS
        int idx = g_ballidx[(long)q * 112 + off + k];
#pragma unroll
        for (int c = 0; c < 3; ++c)
            Xs[c * PT + tid] = g_xyzT[((long)b * 3 + c) * NN + idx] - g_newxyz[(long)q * 3 + c];
        const float4* fr = (const float4*)&g_featsT[((long)b * NN + idx) * CF];
#pragma unroll
        for (int c4 = 0; c4 < CF / 4; ++c4) {
            float4 v = fr[c4];
            Xs[(3 + c4 * 4 + 0) * PT + tid] = v.x;
            Xs[(3 + c4 * 4 + 1) * PT + tid] = v.y;
            Xs[(3 + c4 * 4 + 2) * PT + tid] = v.z;
            Xs[(3 + c4 * 4 + 3) * PT + tid] = v.w;
        }
    } else {
#pragma unroll 4
        for (int i = tid; i < C * (PT / 4); i += 256) {
            int c = i / (PT / 4);
            int col = i - c * (PT / 4);
            float4 v = *(const float4*)&X[(long)c * PTOT + p0 + col * 4];
            if (FOLD) {
                float a = aArr[c], be = bArr[c];
                v.x = fmaxf(0.0f, fmaf(a, v.x, be));
                v.y = fmaxf(0.0f, fmaf(a, v.y, be));
                v.z = fmaxf(0.0f, fmaf(a, v.z, be));
                v.w = fmaxf(0.0f, fmaf(a, v.w, be));
            }
            *(float4*)&Xs[c * PT + col * 4] = v;
        }
    }
    __syncthreads();

    int pg = tid % PG;
    int og = tid / PG;

    unsigned long long accq[TO][TP / 2];
#pragma unroll
    for (int i = 0; i < TO; ++i)
#pragma unroll
        for (int j = 0; j < TP / 2; ++j) accq[i][j] = 0ull;

    // dense split addressing: 16B/lane, conflict-free
    const float* xpA = Xs + pg * 4;
    const float* xpB = Xs + PT / 2 + pg * 4;
    const float* wp = Ws + og * TO;
#pragma unroll 4
    for (int cc = 0; cc < C; ++cc) {
        ulonglong2 xa = *(const ulonglong2*)&xpA[cc * PT];
        ulonglong2 xb = *(const ulonglong2*)&xpB[cc * PT];
        unsigned long long xq0 = xa.x, xq1 = xa.y, xq2 = xb.x, xq3 = xb.y;
        float wv[TO];
        if (TO == 8) {
            float4 w0 = *(const float4*)&wp[cc * OP];
            float4 w1 = *(const float4*)&wp[cc * OP + 4];
            wv[0] = w0.x; wv[1] = w0.y; wv[2] = w0.z; wv[3] = w0.w;
            wv[4] = w1.x; wv[5] = w1.y; wv[6] = w1.z; wv[7] = w1.w;
        } else {
#pragma unroll
            for (int i = 0; i < TO; ++i) wv[i] = wp[cc * OP + i];
        }
#pragma unroll
        for (int i = 0; i < TO; ++i) {
            unsigned long long wq;
            unsigned int wu = __float_as_uint(wv[i]);
            asm("mov.b64 %0, {%1, %1};" : "=l"(wq) : "r"(wu));
            asm("fma.rn.f32x2 %0, %1, %2, %0;" : "+l"(accq[i][0]) : "l"(wq), "l"(xq0));
            asm("fma.rn.f32x2 %0, %1, %2, %0;" : "+l"(accq[i][1]) : "l"(wq), "l"(xq1));
            asm("fma.rn.f32x2 %0, %1, %2, %0;" : "+l"(accq[i][2]) : "l"(wq), "l"(xq2));
            asm("fma.rn.f32x2 %0, %1, %2, %0;" : "+l"(accq[i][3]) : "l"(wq), "l"(xq3));
        }
    }

    // acc[i][0..3] -> cols p0+pg*4+0..3 ; acc[i][4..7] -> cols p0+PT/2+pg*4+0..3
    float acc[TO][TP];
#pragma unroll
    for (int i = 0; i < TO; ++i)
#pragma unroll
        for (int j2 = 0; j2 < TP / 2; ++j2) {
            unsigned int lo, hi;
            asm("mov.b64 {%0, %1}, %2;" : "=r"(lo), "=r"(hi) : "l"(accq[i][j2]));
            acc[i][2 * j2]     = __uint_as_float(lo);
            acc[i][2 * j2 + 1] = __uint_as_float(hi);
        }

    int Wd = 4 << scale;                 // lanes sharing one query (K/4)
    long qA = (p0 - colOff + pg * 4) >> (4 + scale);
    long qB = (p0 - colOff + PT / 2 + pg * 4) >> (4 + scale);

#pragma unroll
    for (int i = 0; i < TO; ++i) {
        int o = og * TO + i;
        float s = 0.0f, sq = 0.0f;
#pragma unroll
        for (int j = 0; j < TP; ++j) {
            float v = acc[i][j];
            s += v;
            sq = fmaf(v, v, sq);
        }
        if (!MAXOUT) {
            float4 v0 = make_float4(acc[i][0], acc[i][1], acc[i][2], acc[i][3]);
            float4 v1 = make_float4(acc[i][4], acc[i][5], acc[i][6], acc[i][7]);
            *(float4*)&Y[(long)o * PTOT + p0 + pg * 4] = v0;
            *(float4*)&Y[(long)o * PTOT + p0 + PT / 2 + pg * 4] = v1;
        }
#pragma unroll
        for (int off = PG / 2; off > 0; off >>= 1) {
            s  += __shfl_down_sync(0xffffffffu, s, off, PG);
            sq += __shfl_down_sync(0xffffffffu, sq, off, PG);
        }
        if (pg == 0) {
            atomicAdd(&statsOut[o], (double)s);
            atomicAdd(&statsOut[128 + o], (double)sq);
        }
        if (MAXOUT) {
            float mxA = fmaxf(fmaxf(acc[i][0], acc[i][1]), fmaxf(acc[i][2], acc[i][3]));
            float mnA = fminf(fminf(acc[i][0], acc[i][1]), fminf(acc[i][2], acc[i][3]));
            float mxB = fmaxf(fmaxf(acc[i][4], acc[i][5]), fmaxf(acc[i][6], acc[i][7]));
            float mnB = fminf(fminf(acc[i][4], acc[i][5]), fminf(acc[i][6], acc[i][7]));
            for (int off = Wd >> 1; off > 0; off >>= 1) {
                mxA = fmaxf(mxA, __shfl_down_sync(0xffffffffu, mxA, off, Wd));
                mnA = fminf(mnA, __shfl_down_sync(0xffffffffu, mnA, off, Wd));
                mxB = fmaxf(mxB, __shfl_down_sync(0xffffffffu, mxB, off, Wd));
                mnB = fminf(mnB, __shfl_down_sync(0xffffffffu, mnB, off, Wd));
            }
            if ((pg & (Wd - 1)) == 0) {
                g_mmax[(long)o * (3 * NQ) + scale * NQ + qA] = mxA;
                g_mmin[(long)o * (3 * NQ) + scale * NQ + qA] = mnA;
                g_mmax[(long)o * (3 * NQ) + scale * NQ + qB] = mxB;
                g_mmin[(long)o * (3 * NQ) + scale * NQ + qB] = mnB;
            }
        }
    }
}

// ---------------- finalize BN params: one block per scale ----------------
__global__ void finalize_kernel(int L, int O, const float* __restrict__ g,
                                const float* __restrict__ b) {
    int s = blockIdx.x;
    int o = threadIdx.x;
    if (o >= O) return;
    long Pc = (s == 0) ? P1 : ((s == 1) ? P2 : P3);
    const double* st = g_stats9[s * 3 + L];
    double m = st[o] / (double)Pc;
    double var = st[128 + o] / (double)Pc - m * m;
    float aa = g[s * O + o] / sqrtf((float)var + 1e-5f);
    g_a9[(s * 3 + L) * 128 + o] = aa;
    g_beta9[(s * 3 + L) * 128 + o] = fmaf(-(float)m, aa, b[s * O + o]);
}

// ---------------- final BN+ReLU on pooled max/min ----------------
__global__ void bn_out_kernel(float* __restrict__ out) {
    int i = blockIdx.x * 256 + threadIdx.x;   // over 3*128*NQ
    int scale = i / (128 * NQ);
    int r = i - scale * (128 * NQ);
    int o = r / NQ;
    int q = r - o * NQ;
    int b = q >> 11, s = q & (SS - 1);
    float a = g_a9[(scale * 3 + 2) * 128 + o];
    float be = g_beta9[(scale * 3 + 2) * 128 + o];
    float mx = g_mmax[(long)o * (3 * NQ) + scale * NQ + q];
    float mn = g_mmin[(long)o * (3 * NQ) + scale * NQ + q];
    float v = (a >= 0.0f) ? mx : mn;
    out[((long)b * OUTCH + scale * 128 + o) * SS + s] = fmaxf(0.0f, fmaf(a, v, be));
}

// ---------------- launch ----------------
extern "C" void kernel_launch(void* const* d_in, const int* in_sizes, int n_in,
                              void* d_out, int out_size) {
    (void)in_sizes; (void)n_in; (void)out_size;
    const float* xyz   = (const float*)d_in[0];
    const float* feats = (const float*)d_in[1];
    const float* w1 = (const float*)d_in[2];
    const float* g1 = (const float*)d_in[3];
    const float* b1 = (const float*)d_in[4];
    const float* w2 = (const float*)d_in[5];
    const float* g2 = (const float*)d_in[6];
    const float* b2 = (const float*)d_in[7];
    const float* w3 = (const float*)d_in[8];
    const float* g3 = (const float*)d_in[9];
    const float* b3 = (const float*)d_in[10];
    float* out = (float*)d_out;
    float* outF = out + (long)BB * SS * 3;

    float *bufA = nullptr, *bufB = nullptr;
    double* stats = nullptr;
    cudaGetSymbolAddress((void**)&bufA, g_bufA);
    cudaGetSymbolAddress((void**)&bufB, g_bufB);
    cudaGetSymbolAddress((void**)&stats, g_stats9);

    cudaFuncSetAttribute(fps_kernel, cudaFuncAttributeMaxDynamicSharedMemorySize, 3 * NN * 4);

    auto g1k = gemm_t<64, 67, 256, 8, 0, false, true, false>;
    auto g2k = gemm_t<96, 64, 128, 6, 1, true, false, false>;
    auto g3k = gemm_t<128, 96, 128, 8, 2, true, false, true>;
    const int smem1 = 67 * 256 * 4 + 67 * 68 * 4;
    const int smem2 = 64 * 128 * 4 + 64 * 100 * 4;
    const int smem3 = 96 * 128 * 4 + 96 * 132 * 4;
    cudaFuncSetAttribute(g1k, cudaFuncAttributeMaxDynamicSharedMemorySize, smem1);
    cudaFuncSetAttribute(g2k, cudaFuncAttributeMaxDynamicSharedMemorySize, smem2);
    cudaFuncSetAttribute(g3k, cudaFuncAttributeMaxDynamicSharedMemorySize, smem3);

    cudaMemsetAsync(stats, 0, 9 * 256 * sizeof(double));

    // kernel launches: 1 fused_prep, 2 fps, 3 ballq, 4 g1k (profiled slot)
    dim3 tb(32, 8), tg(NN / 32, CF / 32, BB);
    fused_prep_kernel<<<tg, tb>>>(feats, xyz);
    fps_kernel<<<BB, 1024, 3 * NN * 4>>>(xyz, out);
    ballq_kernel<<<(BB * SS * 32) / 256, 256>>>();

    g1k<<<PTOT / 256, 256, smem1>>>(w1, nullptr, bufB);
    finalize_kernel<<<3, 128>>>(0, 64, g1, b1);

    g2k<<<PTOT / 128, 256, smem2>>>(w2, bufB, bufA);
    finalize_kernel<<<3, 128>>>(1, 96, g2, b2);

    g3k<<<PTOT / 128, 256, smem3>>>(w3, bufA, nullptr);
    finalize_kernel<<<3, 128>>>(2, 128, g3, b3);

    bn_out_kernel<<<3 * 128 * NQ / 256, 256>>>(outF);
}